// round 17
// baseline (speedup 1.0000x reference)
#include <cuda_runtime.h>
#include <math.h>

#define BB 64
#define SS 1024
#define DD 128
#define HH 20
#define G4 80   // 4*H

typedef unsigned long long u64;

// ---------------- scratch (device globals; no allocations) ----------------
__device__ float g_G[BB * SS * G4];   // input-gemm result + bias   (~21 MB)
__device__ float g_HS[BB * SS * HH];  // LSTM hidden states         (~5.2 MB)
__device__ float g_Sig[BB * SS];
__device__ float g_Mu[BB * SS];

__device__ __forceinline__ float sigmoidf_(float x) {
    return __fdividef(1.0f, 1.0f + __expf(-x));
}

// fast tanh via exp2-based __expf; clamp keeps e finite (c is gate-bounded anyway)
__device__ __forceinline__ float tanhf_fast(float x) {
    float xc = fminf(fmaxf(x, -15.0f), 15.0f);
    float e  = __expf(2.0f * xc);
    return __fdividef(e - 1.0f, e + 1.0f);
}

// ---------------- K1: G[bs,k] = x[bs,:] . W_ih[k,:] + b_ih[k] + b_hh[k] ----
__global__ void k1_ingemm(const float* __restrict__ x,
                          const float* __restrict__ Wih,
                          const float* __restrict__ bih,
                          const float* __restrict__ bhh) {
    __shared__ float xs[64][33];   // +1 pad: kill bank conflicts
    __shared__ float wsm[80][33];

    const int tid  = threadIdx.x;          // 256 threads
    const int row0 = blockIdx.x * 64;
    const int ty   = tid >> 4;             // 0..15 -> 4 rows each
    const int tx   = tid & 15;             // 0..15 -> 5 cols each

    float acc[4][5];
#pragma unroll
    for (int i = 0; i < 4; i++)
#pragma unroll
        for (int j = 0; j < 5; j++) acc[i][j] = 0.0f;

    for (int kc = 0; kc < 128; kc += 32) {
        __syncthreads();
        for (int i = tid; i < 64 * 8; i += 256) {
            int r = i >> 3, c4 = i & 7;
            float4 v = *(const float4*)&x[(size_t)(row0 + r) * 128 + kc + c4 * 4];
            xs[r][c4 * 4 + 0] = v.x; xs[r][c4 * 4 + 1] = v.y;
            xs[r][c4 * 4 + 2] = v.z; xs[r][c4 * 4 + 3] = v.w;
        }
        for (int i = tid; i < 80 * 8; i += 256) {
            int r = i >> 3, c4 = i & 7;
            float4 v = *(const float4*)&Wih[(size_t)r * 128 + kc + c4 * 4];
            wsm[r][c4 * 4 + 0] = v.x; wsm[r][c4 * 4 + 1] = v.y;
            wsm[r][c4 * 4 + 2] = v.z; wsm[r][c4 * 4 + 3] = v.w;
        }
        __syncthreads();

#pragma unroll 8
        for (int k = 0; k < 32; k++) {
            float xa[4], wb[5];
#pragma unroll
            for (int i = 0; i < 4; i++) xa[i] = xs[ty * 4 + i][k];
#pragma unroll
            for (int j = 0; j < 5; j++) wb[j] = wsm[tx * 5 + j][k];
#pragma unroll
            for (int i = 0; i < 4; i++)
#pragma unroll
                for (int j = 0; j < 5; j++)
                    acc[i][j] = fmaf(xa[i], wb[j], acc[i][j]);
        }
    }

#pragma unroll
    for (int i = 0; i < 4; i++) {
        int r = row0 + ty * 4 + i;
#pragma unroll
        for (int j = 0; j < 5; j++) {
            int c = tx * 5 + j;
            g_G[(size_t)r * G4 + c] = acc[i][j] + __ldg(&bih[c]) + __ldg(&bhh[c]);
        }
    }
}

// ---------------- K2: LSTM recurrence (1 block of 128 threads per batch) ---
// depth-4 register prefetch of G: load for step s+4 issues at step s,
// giving ~3 iterations of latency slack (covers DRAM-tier ~577 cyc).
__global__ void k2_lstm(const float* __restrict__ Whh) {
    const int b = blockIdx.x;
    const int k = threadIdx.x;      // 0..127 ; gates use k < 80

    __shared__ float sh[HH];        // h_t
    __shared__ float sg[G4];        // gate pre-activations

    float w[HH];
    if (k < G4) {
#pragma unroll
        for (int m = 0; m < HH; m++) w[m] = Whh[k * HH + m];
    }
    float c = 0.0f;
    if (k < HH) sh[k] = 0.0f;
    __syncthreads();

    const float* Gb = g_G + (size_t)b * SS * G4;
    float gin[4];
#pragma unroll
    for (int q = 0; q < 4; q++)
        gin[q] = (k < G4) ? Gb[(size_t)q * G4 + k] : 0.0f;

    for (int s = 0; s < SS; s++) {
        float ginN = 0.0f;
        if (k < G4 && s + 4 < SS) ginN = Gb[(size_t)(s + 4) * G4 + k];

        if (k < G4) {
            float a0 = gin[0], a1 = 0.0f, a2 = 0.0f, a3 = 0.0f;
#pragma unroll
            for (int m = 0; m < HH; m += 4) {
                a0 = fmaf(w[m + 0], sh[m + 0], a0);
                a1 = fmaf(w[m + 1], sh[m + 1], a1);
                a2 = fmaf(w[m + 2], sh[m + 2], a2);
                a3 = fmaf(w[m + 3], sh[m + 3], a3);
            }
            sg[k] = (a0 + a1) + (a2 + a3);
        }
        __syncthreads();

        if (k < HH) {
            float ig = sigmoidf_(sg[k]);
            float fg = sigmoidf_(sg[HH + k]);
            float gg = tanhf_fast(sg[2 * HH + k]);
            float og = sigmoidf_(sg[3 * HH + k]);
            c = fmaf(fg, c, ig * gg);
            float hn = og * tanhf_fast(c);
            sh[k] = hn;
            g_HS[((size_t)b * SS + s) * HH + k] = hn;
        }
        __syncthreads();
        gin[0] = gin[1]; gin[1] = gin[2]; gin[2] = gin[3]; gin[3] = ginN;
    }
}

// ---------------- K34: heads + mu linear-recurrence scan (1 block / batch) -
__global__ void __launch_bounds__(256) k34_projscan(
        const float* __restrict__ Wmu, const float* __restrict__ bmu,
        const float* __restrict__ Wsig, const float* __restrict__ bsig) {
    const int b    = blockIdx.x;       // 64 blocks
    const int tid  = threadIdx.x;      // 256 threads, 4 consecutive j each
    const int lane = tid & 31;
    const int warp = tid >> 5;
    const int j0   = tid * 4;

    float wm0[HH], wm1[HH], wm2[HH], wsg[HH];
#pragma unroll
    for (int m = 0; m < HH; m++) {
        wm0[m] = __ldg(&Wmu[m]);
        wm1[m] = __ldg(&Wmu[HH + m]);
        wm2[m] = __ldg(&Wmu[2 * HH + m]);
        wsg[m] = __ldg(&Wsig[m]);
    }
    const float b0 = __ldg(&bmu[0]), b1 = __ldg(&bmu[1]), b2 = __ldg(&bmu[2]);
    const float bs = __ldg(&bsig[0]);

    float av[4], cv[4];
#pragma unroll
    for (int q = 0; q < 4; q++) {
        const int j = j0 + q;
        const float* h = g_HS + ((size_t)b * SS + j) * HH;
        float d0 = b0, d1 = b1, d2 = b2, ds = bs;
#pragma unroll
        for (int m = 0; m < HH; m++) {
            float hv = h[m];
            d0 = fmaf(wm0[m], hv, d0);
            d1 = fmaf(wm1[m], hv, d1);
            d2 = fmaf(wm2[m], hv, d2);
            ds = fmaf(wsg[m], hv, ds);
        }
        av[q] = fmaxf(d0, 0.0f);
        float m1 = fmaxf(d1, 0.0f);
        float m2 = fmaxf(d2, 0.0f);
        cv[q] = m1 * (1.0f / SS) + m2 * ((float)(j + 1) * (1.0f / SS));
        g_Sig[(size_t)b * SS + j] = sigmoidf_(ds);
    }

    float A = av[0], C = cv[0];
#pragma unroll
    for (int q = 1; q < 4; q++) {
        C = fmaf(av[q], C, cv[q]);
        A = av[q] * A;
    }

#pragma unroll
    for (int d = 1; d < 32; d <<= 1) {
        float Ap = __shfl_up_sync(0xffffffffu, A, d);
        float Cp = __shfl_up_sync(0xffffffffu, C, d);
        if (lane >= d) { C = fmaf(A, Cp, C); A = A * Ap; }
    }

    __shared__ float sA[8], sC[8];
    __shared__ float wAp[8], wCp[8];
    if (lane == 31) { sA[warp] = A; sC[warp] = C; }

    float Aexc = __shfl_up_sync(0xffffffffu, A, 1);
    float Cexc = __shfl_up_sync(0xffffffffu, C, 1);
    if (lane == 0) { Aexc = 1.0f; Cexc = 0.0f; }

    __syncthreads();
    if (tid == 0) {
        float pA = 1.0f, pC = 0.0f;
        for (int wI = 0; wI < 8; wI++) {
            wAp[wI] = pA; wCp[wI] = pC;
            float nC = fmaf(sA[wI], pC, sC[wI]);
            pA = sA[wI] * pA;
            pC = nC;
        }
    }
    __syncthreads();

    float PC = fmaf(Aexc, wCp[warp], Cexc);
    float mu = PC;
#pragma unroll
    for (int q = 0; q < 4; q++) {
        mu = fmaf(av[q], mu, cv[q]);
        g_Mu[(size_t)b * SS + j0 + q] = mu;
    }
}

// ---------------- K5: triangular weighted sum + L2 norm, packed f32x2 FMA --
// grid (16, 64): blockIdx.y = b, j-tile index = 15 - blockIdx.x (heavy first)
__global__ void __launch_bounds__(256) k5_attn(const float* __restrict__ x,
                                               float* __restrict__ out) {
    __shared__ __align__(16) float xs[64][128];   // 32 KB
    __shared__ __align__(16) float ws[64][64];    // 16 KB  (total = 48 KB)

    const int tid = threadIdx.x;
    const int b   = blockIdx.y;
    const int jt  = (int)gridDim.x - 1 - (int)blockIdx.x;
    const int j0  = jt * 64;

    const int wj    = tid & 63;
    const int chunk = tid >> 6;            // 0..3, each covers 16 t's per tile
    const int jg    = j0 + wj;
    const float mu     = g_Mu[(size_t)b * SS + jg];
    const float sgv    = g_Sig[(size_t)b * SS + jg];
    const float inv2s2 = 1.0f / (2.0f * sgv * sgv);
    const float invj1  = 1.0f / (float)(jg + 1);
    float w2 = 0.0f;

    const int jl0 = (tid & 15) * 4;
    const int dd0 = (tid >> 4) * 8;

    // packed accumulators: acc2[jj][p] = (acc[jj][2p], acc[jj][2p+1])
    u64 acc2[4][4];
#pragma unroll
    for (int i = 0; i < 4; i++)
#pragma unroll
        for (int p = 0; p < 4; p++) acc2[i][p] = 0ull;

    const float4* xg4 = (const float4*)(x + (size_t)b * SS * DD);

    for (int tt = 0; tt <= jt; tt++) {
        const int t0 = tt * 64;
        __syncthreads();

#pragma unroll
        for (int i = 0; i < 8; i++) {
            int idx = tid + i * 256;
            ((float4*)xs)[idx] = xg4[t0 * 32 + idx];
        }
#pragma unroll
        for (int it = 0; it < 16; it++) {
            int tl = chunk * 16 + it;
            int t  = t0 + tl;
            float dlt = fmaf((float)t, invj1, -mu);
            float e   = dlt * dlt * inv2s2;
            float wv  = (t <= jg) ? __expf(-e) : 0.0f;
            ws[tl][wj] = wv;
            w2 = fmaf(wv, wv, w2);
        }
        __syncthreads();

        // packed-f32x2 register GEMM: acc[j][d] += w[t][j] * x[t][d]
#pragma unroll 8
        for (int t = 0; t < 64; t++) {
            float4 wv = *(const float4*)&ws[t][jl0];
            ulonglong2 xa = *(const ulonglong2*)&xs[t][dd0];
            ulonglong2 xb = *(const ulonglong2*)&xs[t][dd0 + 4];
            u64 xr[4] = {xa.x, xa.y, xb.x, xb.y};
            u64 wp[4];
            {
                unsigned int u0 = __float_as_uint(wv.x);
                unsigned int u1 = __float_as_uint(wv.y);
                unsigned int u2 = __float_as_uint(wv.z);
                unsigned int u3 = __float_as_uint(wv.w);
                asm("mov.b64 %0, {%1, %1};" : "=l"(wp[0]) : "r"(u0));
                asm("mov.b64 %0, {%1, %1};" : "=l"(wp[1]) : "r"(u1));
                asm("mov.b64 %0, {%1, %1};" : "=l"(wp[2]) : "r"(u2));
                asm("mov.b64 %0, {%1, %1};" : "=l"(wp[3]) : "r"(u3));
            }
#pragma unroll
            for (int jj = 0; jj < 4; jj++)
#pragma unroll
                for (int p = 0; p < 4; p++)
                    asm("fma.rn.f32x2 %0, %1, %2, %3;"
                        : "=l"(acc2[jj][p])
                        : "l"(wp[jj]), "l"(xr[p]), "l"(acc2[jj][p]));
        }
    }

    __syncthreads();
    float* w2p = &ws[0][0];
    w2p[chunk * 64 + wj] = w2;
    __syncthreads();

#pragma unroll
    for (int jj = 0; jj < 4; jj++) {
        int jl = jl0 + jj;
        float s2  = w2p[jl] + w2p[64 + jl] + w2p[128 + jl] + w2p[192 + jl];
        float inv = 1.0f / fmaxf(sqrtf(s2), 1e-12f);
        float o[8];
#pragma unroll
        for (int p = 0; p < 4; p++) {
            unsigned int lo, hi;
            asm("mov.b64 {%0, %1}, %2;" : "=r"(lo), "=r"(hi) : "l"(acc2[jj][p]));
            o[2 * p]     = __uint_as_float(lo) * inv;
            o[2 * p + 1] = __uint_as_float(hi) * inv;
        }
        float4 o0 = {o[0], o[1], o[2], o[3]};
        float4 o1 = {o[4], o[5], o[6], o[7]};
        size_t base = ((size_t)b * SS + (j0 + jl)) * DD + dd0;
        *(float4*)&out[base]     = o0;
        *(float4*)&out[base + 4] = o1;
    }
}

// ---------------- launch ---------------------------------------------------
extern "C" void kernel_launch(void* const* d_in, const int* in_sizes, int n_in,
                              void* d_out, int out_size) {
    const float* x    = (const float*)d_in[0];
    const float* Wih  = (const float*)d_in[1];
    const float* Whh  = (const float*)d_in[2];
    const float* bih  = (const float*)d_in[3];
    const float* bhh  = (const float*)d_in[4];
    const float* Wmu  = (const float*)d_in[5];
    const float* bmu  = (const float*)d_in[6];
    const float* Wsig = (const float*)d_in[7];
    const float* bsig = (const float*)d_in[8];
    float* out = (float*)d_out;

    k1_ingemm<<<(BB * SS) / 64, 256>>>(x, Wih, bih, bhh);
    k2_lstm<<<BB, 128>>>(Whh);
    k34_projscan<<<BB, 256>>>(Wmu, bmu, Wsig, bsig);
    k5_attn<<<dim3(SS / 64, BB), 256>>>(x, out);
}